// round 10
// baseline (speedup 1.0000x reference)
#include <cuda_runtime.h>

// Problem constants (from reference setup_inputs)
#define Bc    4
#define Nc    16384
#define Kc    27
#define BNc   (Bc * Nc)            // 65536
#define Tc    (BNc * Kc)           // 1769472
#define BASEc 70
#define BASE3 343000               // 70^3
#define TABLE_SIZE (Bc * BASE3)    // 1372000
#define SHIFTc 3

#define NWORDS (Tc / 32)           // 55296 bitmask words (exact)
#define SCAN_CHUNK 54              // 1024 threads * 54 = 55296 (exact)

// Scratch (__device__ globals). Addresses formed ONLY in device code
// (round-7 lesson: host-side &g_sym is the shadow symbol; ATS hides the bug).
__device__ __align__(16) int g_table[TABLE_SIZE];     // min t per key (INT_MAX empty)
__device__ int g_oi[TABLE_SIZE];                      // dense rank per key
__device__ int g_keybase[BNc];                        // encoded center key per point
__device__ __align__(16) unsigned g_bits[NWORDS];     // bit t set <=> first occurrence
__device__ int g_wordpre[NWORDS];                     // GLOBAL exclusive popc prefix per word
__device__ int g_numout;                              // unique key count

// key delta per kernel offset k ('ij' meshgrid order)
__constant__ int c_delta[Kc] = {
    -4971, -4970, -4969,  -4901, -4900, -4899,  -4831, -4830, -4829,
      -71,   -70,   -69,     -1,     0,     1,     69,    70,    71,
     4829,  4830,  4831,   4899,  4900,  4901,   4969,  4970,  4971
};

// Table init only (5.5 MB, int4).
__global__ void k_prep() {
    int i = blockIdx.x * blockDim.x + threadIdx.x;
    if (i < TABLE_SIZE / 4)
        ((int4*)g_table)[i] = make_int4(0x7fffffff, 0x7fffffff, 0x7fffffff, 0x7fffffff);
}

// zero any harness padding past 6T+1 (launched only when present)
__global__ void k_tail(float* __restrict__ p, long long n) {
    long long i = (long long)blockIdx.x * blockDim.x + threadIdx.x;
    long long stride = (long long)gridDim.x * blockDim.x;
    for (; i < n; i += stride) p[i] = 0.0f;
}

// One thread per (point, offset): 1 spread atomic each. Also zeroes g_bits
// (needed only by the NEXT launch, no intra-kernel interaction).
__global__ void k_build(const int* __restrict__ coords,
                        const int* __restrict__ batch) {
    int t = blockIdx.x * blockDim.x + threadIdx.x;
    if (t >= Tc) return;
    if (t < NWORDS) g_bits[t] = 0u;
    int idx = t / Kc;
    int k   = t - idx * Kc;
    int x = coords[idx * 3 + 0];
    int y = coords[idx * 3 + 1];
    int z = coords[idx * 3 + 2];
    int b = batch[idx];
    int kb = b * BASE3 + ((x + SHIFTc) * BASEc + (y + SHIFTc)) * BASEc + (z + SHIFTc);
    if (k == 0) g_keybase[idx] = kb;
    atomicMin(&g_table[kb + c_delta[k]], t);
}

// Table pass: occupied key -> set bit at its min-t.
__global__ void k_bitset() {
    int i = blockIdx.x * blockDim.x + threadIdx.x;
    if (i >= TABLE_SIZE / 4) return;
    int4 v = ((const int4*)g_table)[i];
#pragma unroll
    for (int j = 0; j < 4; j++) {
        int ft = (&v.x)[j];
        if (ft != 0x7fffffff)
            atomicOr(&g_bits[ft >> 5], 1u << (ft & 31));
    }
}

// Single-block global scan: per-word GLOBAL exclusive prefix + num_out.
__global__ void k_scan(float* __restrict__ out) {
    __shared__ int wsum[32];
    int tid = threadIdx.x;            // 1024 threads
    int base = tid * SCAN_CHUNK;

    int s = 0;
#pragma unroll
    for (int j = 0; j < SCAN_CHUNK; j++) s += __popc(g_bits[base + j]);

    int lane = tid & 31, wid = tid >> 5;
    int incl = s;
#pragma unroll
    for (int d = 1; d < 32; d <<= 1) {
        int v = __shfl_up_sync(0xffffffffu, incl, d);
        if (lane >= d) incl += v;
    }
    if (lane == 31) wsum[wid] = incl;
    __syncthreads();
    if (wid == 0) {
        int v = (lane < 32) ? wsum[lane] : 0;
#pragma unroll
        for (int d = 1; d < 32; d <<= 1) {
            int u = __shfl_up_sync(0xffffffffu, v, d);
            if (lane >= d) v += u;
        }
        wsum[lane] = v;
    }
    __syncthreads();

    int run = ((wid == 0) ? 0 : wsum[wid - 1]) + incl - s;   // global exclusive
#pragma unroll
    for (int j = 0; j < SCAN_CHUNK; j++) {
        g_wordpre[base + j] = run;
        run += __popc(g_bits[base + j]);
    }
    if (tid == 1023) {                       // run == grand total here
        g_numout = run;
        out[6LL * Tc] = (float)run;          // num_out
    }
}

// Table pass: occupied key -> rank via bitmask prefix; write g_oi + out_key.
__global__ void k_assign(float* __restrict__ out) {
    int i = blockIdx.x * blockDim.x + threadIdx.x;
    if (i >= TABLE_SIZE / 4) return;
    int4 v = ((const int4*)g_table)[i];
#pragma unroll
    for (int j = 0; j < 4; j++) {
        int ft = (&v.x)[j];
        if (ft == 0x7fffffff) continue;
        int key = i * 4 + j;
        int w = ft >> 5;
        unsigned mask = (1u << (ft & 31)) - 1u;
        int rank = g_wordpre[w] + __popc(g_bits[w] & mask);
        g_oi[key] = rank;
        int rem = key % BASE3;
        int xx = rem / (BASEc * BASEc) - SHIFTc;
        int yy = (rem / BASEc) % BASEc - SHIFTc;
        int zz = rem % BASEc - SHIFTc;
        float* p = out + 3LL * Tc + 3LL * rank;
        p[0] = (float)xx; p[1] = (float)yy; p[2] = (float)zz;
    }
}

// Final pass: in_idx, out_idx, rel_pos (float4 streams) + out_key -1 padding
// for rows [num_out, Tc) — valid rows were written by k_assign.
__global__ void k_outidx(float* __restrict__ out) {
    int i = blockIdx.x * blockDim.x + threadIdx.x;
    if (i >= Tc / 4) return;
    int t0 = i * 4;
    int no = g_numout;                 // broadcast load
    float4 a, b, c;
#pragma unroll
    for (int j = 0; j < 4; j++) {
        int t   = t0 + j;
        int idx = t / Kc;
        int k   = t - idx * Kc;
        int key = g_keybase[idx] + c_delta[k];
        (&a.x)[j] = (float)(idx & (Nc - 1));
        (&b.x)[j] = (float)g_oi[key];
        (&c.x)[j] = (float)k;
    }
    ((float4*)out)[i]              = a;   // in_idx
    ((float4*)(out + 1LL * Tc))[i] = b;   // out_idx
    ((float4*)(out + 2LL * Tc))[i] = c;   // rel_pos

    // out_key padding: rows t0..t0+3 <-> floats [12i, 12i+12)
    if (t0 >= no) {                        // all 4 rows padded: 3x float4
        float4 m1 = make_float4(-1.f, -1.f, -1.f, -1.f);
        float4* p = (float4*)(out + 3LL * Tc + 12LL * i);
        p[0] = m1; p[1] = m1; p[2] = m1;
    } else if (t0 + 3 >= no) {             // boundary thread: scalar
#pragma unroll
        for (int j = 0; j < 4; j++) {
            int t = t0 + j;
            if (t >= no) {
                float* p = out + 3LL * Tc + 3LL * t;
                p[0] = -1.f; p[1] = -1.f; p[2] = -1.f;
            }
        }
    }
}

extern "C" void kernel_launch(void* const* d_in, const int* in_sizes, int n_in,
                              void* d_out, int out_size) {
    // Identify inputs by SIZE: coordinates = [B,N,3] (3*BNc), batch = [B,N] (BNc).
    const int* coords = (const int*)d_in[0];
    const int* batch  = (const int*)d_in[n_in > 1 ? 1 : 0];
    for (int i = 0; i < n_in; i++) {
        if (in_sizes[i] == 3 * BNc) coords = (const int*)d_in[i];
        else if (in_sizes[i] == BNc) batch = (const int*)d_in[i];
    }
    float* out = (float*)d_out;
    long long osz = (long long)out_size;

    long long tail = osz - (6LL * Tc + 1);
    if (tail > 0) k_tail<<<512, 256>>>(out + 6LL * Tc + 1, tail);

    k_prep<<<(TABLE_SIZE / 4 + 255) / 256, 256>>>();
    k_build<<<(Tc + 255) / 256, 256>>>(coords, batch);
    k_bitset<<<(TABLE_SIZE / 4 + 255) / 256, 256>>>();
    k_scan<<<1, 1024>>>(out);
    k_assign<<<(TABLE_SIZE / 4 + 255) / 256, 256>>>(out);
    k_outidx<<<(Tc / 4 + 255) / 256, 256>>>(out);
}

// round 11
// speedup vs baseline: 1.4411x; 1.4411x over previous
#include <cuda_runtime.h>

// Problem constants (from reference setup_inputs)
#define Bc    4
#define Nc    16384
#define Kc    27
#define BNc   (Bc * Nc)            // 65536
#define Tc    (BNc * Kc)           // 1769472
#define BASEc 70
#define BASE3 343000               // 70^3
#define TABLE_SIZE (Bc * BASE3)    // 1372000
#define SHIFTc 3

#define NWORDS (Tc / 32)           // 55296 bitmask words (exact)
#define S1_BLOCKS (NWORDS / 256)   // 216 (exact)

#define GRID   592                 // 148 SMs x 4 CTAs — one resident wave
#define NTHR   (GRID * 256)        // 151552

// Scratch (__device__ globals; addresses formed only in device code).
__device__ __align__(16) int g_table[TABLE_SIZE];     // min t per key (INT_MAX empty)
__device__ int g_oi[TABLE_SIZE];                      // dense rank per key
__device__ int g_keybase[BNc];                        // encoded center key per point
__device__ __align__(16) unsigned g_bits[NWORDS];     // bit t set <=> first occurrence
__device__ int g_wordpre[NWORDS];                     // intra-tile exclusive popc prefix
__device__ int g_bsum2[S1_BLOCKS];                    // per-tile popc totals
__device__ int g_bpre2[S1_BLOCKS];                    // exclusive prefix of tile totals
__device__ int g_numout;                              // unique key count
__device__ int g_bar;                                 // grid barrier counter (reset by k_reset)

// key delta per kernel offset k ('ij' meshgrid order)
__constant__ int c_delta[Kc] = {
    -4971, -4970, -4969,  -4901, -4900, -4899,  -4831, -4830, -4829,
      -71,   -70,   -69,     -1,     0,     1,     69,    70,    71,
     4829,  4830,  4831,   4899,  4900,  4901,   4969,  4970,  4971
};

// Software grid barrier: monotonic counter; all GRID blocks resident (one wave).
__device__ __forceinline__ void gsync(int target) {
    __syncthreads();
    if (threadIdx.x == 0) {
        __threadfence();
        atomicAdd(&g_bar, 1);
        while (*(volatile int*)&g_bar < target) { }
        __threadfence();
    }
    __syncthreads();
}

// zero any harness padding past 6T+1 (launched only when present)
__global__ void k_tail(float* __restrict__ p, long long n) {
    long long i = (long long)blockIdx.x * blockDim.x + threadIdx.x;
    long long stride = (long long)gridDim.x * blockDim.x;
    for (; i < n; i += stride) p[i] = 0.0f;
}

__global__ void k_reset() { g_bar = 0; }

__global__ void __launch_bounds__(256, 4)
k_main(const int* __restrict__ coords, const int* __restrict__ batch,
       float* __restrict__ out) {
    const int gtid = blockIdx.x * 256 + threadIdx.x;
    const int tid  = threadIdx.x;
    const int lane = tid & 31, wid = tid >> 5;
    __shared__ int wsum[8];
    __shared__ int sh[256];

    // ---- P0: init table to INT_MAX, bits to 0 (int4) ----
    for (int i = gtid; i < TABLE_SIZE / 4; i += NTHR)
        ((int4*)g_table)[i] = make_int4(0x7fffffff, 0x7fffffff, 0x7fffffff, 0x7fffffff);
    for (int i = gtid; i < NWORDS / 4; i += NTHR)
        ((int4*)g_bits)[i] = make_int4(0, 0, 0, 0);
    gsync(GRID * 1);

    // ---- P1: build (atomicMin of t per neighbor key) ----
    for (int t = gtid; t < Tc; t += NTHR) {
        int idx = t / Kc;
        int k   = t - idx * Kc;
        int x = coords[idx * 3 + 0];
        int y = coords[idx * 3 + 1];
        int z = coords[idx * 3 + 2];
        int b = batch[idx];
        int kb = b * BASE3 + ((x + SHIFTc) * BASEc + (y + SHIFTc)) * BASEc + (z + SHIFTc);
        if (k == 0) g_keybase[idx] = kb;
        atomicMin(&g_table[kb + c_delta[k]], t);
    }
    gsync(GRID * 2);

    // ---- P2: bitset (occupied key -> bit at its min-t) ----
    for (int i = gtid; i < TABLE_SIZE / 4; i += NTHR) {
        int4 v = ((const int4*)g_table)[i];
#pragma unroll
        for (int j = 0; j < 4; j++) {
            int ft = (&v.x)[j];
            if (ft != 0x7fffffff)
                atomicOr(&g_bits[ft >> 5], 1u << (ft & 31));
        }
    }
    gsync(GRID * 3);

    // ---- P3: scan level-1 (blocks 0..215, 256 words each) ----
    if (blockIdx.x < S1_BLOCKS) {
        int w = blockIdx.x * 256 + tid;
        int c = __popc(g_bits[w]);
        int incl = c;
#pragma unroll
        for (int d = 1; d < 32; d <<= 1) {
            int v = __shfl_up_sync(0xffffffffu, incl, d);
            if (lane >= d) incl += v;
        }
        if (lane == 31) wsum[wid] = incl;
        __syncthreads();
        if (wid == 0) {
            int v = (lane < 8) ? wsum[lane] : 0;
#pragma unroll
            for (int d = 1; d < 8; d <<= 1) {
                int u = __shfl_up_sync(0xffffffffu, v, d);
                if (lane >= d) v += u;
            }
            if (lane < 8) wsum[lane] = v;
        }
        __syncthreads();
        g_wordpre[w] = ((wid == 0) ? 0 : wsum[wid - 1]) + incl - c;
        if (tid == 255) g_bsum2[blockIdx.x] = wsum[7];
    }
    gsync(GRID * 4);

    // ---- P4: scan level-2 (block 0 over 216 tile totals) ----
    if (blockIdx.x == 0) {
        int v = (tid < S1_BLOCKS) ? g_bsum2[tid] : 0;
        sh[tid] = v;
        __syncthreads();
#pragma unroll
        for (int d = 1; d < 256; d <<= 1) {
            int u = (tid >= d) ? sh[tid - d] : 0;
            __syncthreads();
            sh[tid] += u;
            __syncthreads();
        }
        if (tid < S1_BLOCKS) g_bpre2[tid] = sh[tid] - v;
        if (tid == S1_BLOCKS - 1) {
            g_numout = sh[tid];
            out[6LL * Tc] = (float)sh[tid];          // num_out
        }
    }
    gsync(GRID * 5);

    // ---- P5: assign rank per occupied key; write g_oi + out_key ----
    for (int i = gtid; i < TABLE_SIZE / 4; i += NTHR) {
        int4 v = ((const int4*)g_table)[i];
#pragma unroll
        for (int j = 0; j < 4; j++) {
            int ft = (&v.x)[j];
            if (ft == 0x7fffffff) continue;
            int key = i * 4 + j;
            int w = ft >> 5;
            unsigned mask = (1u << (ft & 31)) - 1u;
            int rank = g_bpre2[w >> 8] + g_wordpre[w] + __popc(g_bits[w] & mask);
            g_oi[key] = rank;
            int rem = key % BASE3;
            int xx = rem / (BASEc * BASEc) - SHIFTc;
            int yy = (rem / BASEc) % BASEc - SHIFTc;
            int zz = rem % BASEc - SHIFTc;
            float* p = out + 3LL * Tc + 3LL * rank;
            p[0] = (float)xx; p[1] = (float)yy; p[2] = (float)zz;
        }
    }
    gsync(GRID * 6);

    // ---- P6: in_idx / out_idx / rel_pos (float4) + out_key -1 padding ----
    int no = g_numout;
    for (int i = gtid; i < Tc / 4; i += NTHR) {
        int t0 = i * 4;
        float4 a, b, c;
#pragma unroll
        for (int j = 0; j < 4; j++) {
            int t   = t0 + j;
            int idx = t / Kc;
            int k   = t - idx * Kc;
            int key = g_keybase[idx] + c_delta[k];
            (&a.x)[j] = (float)(idx & (Nc - 1));
            (&b.x)[j] = (float)g_oi[key];
            (&c.x)[j] = (float)k;
        }
        ((float4*)out)[i]              = a;   // in_idx
        ((float4*)(out + 1LL * Tc))[i] = b;   // out_idx
        ((float4*)(out + 2LL * Tc))[i] = c;   // rel_pos

        if (t0 >= no) {                        // fully padded row group: 3x float4
            float4 m1 = make_float4(-1.f, -1.f, -1.f, -1.f);
            float4* p = (float4*)(out + 3LL * Tc + 12LL * i);
            p[0] = m1; p[1] = m1; p[2] = m1;
        } else if (t0 + 3 >= no) {             // boundary: scalar
#pragma unroll
            for (int j = 0; j < 4; j++) {
                int t = t0 + j;
                if (t >= no) {
                    float* p = out + 3LL * Tc + 3LL * t;
                    p[0] = -1.f; p[1] = -1.f; p[2] = -1.f;
                }
            }
        }
    }
}

extern "C" void kernel_launch(void* const* d_in, const int* in_sizes, int n_in,
                              void* d_out, int out_size) {
    // Identify inputs by SIZE: coordinates = [B,N,3] (3*BNc), batch = [B,N] (BNc).
    const int* coords = (const int*)d_in[0];
    const int* batch  = (const int*)d_in[n_in > 1 ? 1 : 0];
    for (int i = 0; i < n_in; i++) {
        if (in_sizes[i] == 3 * BNc) coords = (const int*)d_in[i];
        else if (in_sizes[i] == BNc) batch = (const int*)d_in[i];
    }
    float* out = (float*)d_out;
    long long osz = (long long)out_size;

    long long tail = osz - (6LL * Tc + 1);
    if (tail > 0) k_tail<<<512, 256>>>(out + 6LL * Tc + 1, tail);

    k_main<<<GRID, 256>>>(coords, batch, out);
    k_reset<<<1, 1>>>();   // rearm the grid barrier for the next graph replay
}

// round 12
// speedup vs baseline: 1.5740x; 1.0922x over previous
#include <cuda_runtime.h>

// Problem constants (from reference setup_inputs)
#define Bc    4
#define Nc    16384
#define Kc    27
#define BNc   (Bc * Nc)            // 65536
#define Tc    (BNc * Kc)           // 1769472
#define BASEc 70
#define BASE3 343000               // 70^3
#define TABLE_SIZE (Bc * BASE3)    // 1372000
#define SHIFTc 3

#define NWORDS (Tc / 32)           // 55296 bitmask words (exact)
#define S1_BLOCKS (NWORDS / 256)   // 216 (exact)

#define GRID   592                 // 148 SMs x 4 CTAs — one resident wave
#define NTHR   (GRID * 256)        // 151552

// Scratch (__device__ globals; addresses formed only in device code — r7 lesson).
// 64-bit epoch-tagged table: value = (epoch<<32)|(Tc-1-t); atomicMax == min-t.
// Stale epochs lose automatically => NO per-call table init.
__device__ __align__(16) unsigned long long g_table[TABLE_SIZE];
__device__ int g_oi[TABLE_SIZE];                      // dense rank per key
__device__ int g_keybase[BNc];                        // encoded center key per point
__device__ __align__(16) unsigned g_bits[NWORDS];     // bit t set <=> first occurrence
__device__ int g_wordpre[NWORDS];                     // intra-tile exclusive popc prefix
__device__ int g_bsum2[S1_BLOCKS];                    // per-tile popc totals
__device__ int g_bpre2[S1_BLOCKS];                    // exclusive prefix of tile totals
__device__ int g_numout;                              // unique key count
__device__ int g_bar;                                 // grid barrier counter
__device__ int g_cnt;                                 // scan1 completion counter
__device__ unsigned g_epoch;                          // call epoch (bumped by k_epoch)

// key delta per kernel offset k ('ij' meshgrid order)
__constant__ int c_delta[Kc] = {
    -4971, -4970, -4969,  -4901, -4900, -4899,  -4831, -4830, -4829,
      -71,   -70,   -69,     -1,     0,     1,     69,    70,    71,
     4829,  4830,  4831,   4899,  4900,  4901,   4969,  4970,  4971
};

// Grid barrier: monotonic counter, one poller per block, nanosleep backoff.
__device__ __forceinline__ void gsync(int target) {
    __syncthreads();
    if (threadIdx.x == 0) {
        __threadfence();
        atomicAdd(&g_bar, 1);
        while (*(volatile int*)&g_bar < target) __nanosleep(128);
        __threadfence();
    }
    __syncthreads();
}

// zero any harness padding past 6T+1 (launched only when present)
__global__ void k_tail(float* __restrict__ p, long long n) {
    long long i = (long long)blockIdx.x * blockDim.x + threadIdx.x;
    long long stride = (long long)gridDim.x * blockDim.x;
    for (; i < n; i += stride) p[i] = 0.0f;
}

// Runs BEFORE k_main each call: bump epoch, rearm barrier + scan counter.
__global__ void k_epoch() { g_epoch++; g_bar = 0; g_cnt = 0; }

__global__ void __launch_bounds__(256, 4)
k_main(const int* __restrict__ coords, const int* __restrict__ batch,
       float* __restrict__ out) {
    const int gtid = blockIdx.x * 256 + threadIdx.x;
    const int tid  = threadIdx.x;
    const int lane = tid & 31, wid = tid >> 5;
    const unsigned ep = g_epoch;
    __shared__ int wsum[8];
    __shared__ int sh[256];
    __shared__ int sh_pos;

    // ---- P1: zero bits (independent) + build (epoch-tagged atomicMax) ----
    for (int i = gtid; i < NWORDS / 4; i += NTHR)
        ((int4*)g_bits)[i] = make_int4(0, 0, 0, 0);
    for (int t = gtid; t < Tc; t += NTHR) {
        int idx = t / Kc;
        int k   = t - idx * Kc;
        int x = coords[idx * 3 + 0];
        int y = coords[idx * 3 + 1];
        int z = coords[idx * 3 + 2];
        int b = batch[idx];
        int kb = b * BASE3 + ((x + SHIFTc) * BASEc + (y + SHIFTc)) * BASEc + (z + SHIFTc);
        if (k == 0) g_keybase[idx] = kb;
        unsigned long long v = ((unsigned long long)ep << 32) | (unsigned)(Tc - 1 - t);
        atomicMax(&g_table[kb + c_delta[k]], v);
    }
    gsync(GRID * 1);

    // ---- P2: bitset — occupied (this epoch) key -> bit at its min-t ----
    for (int i = gtid; i < TABLE_SIZE / 2; i += NTHR) {
        ulonglong2 v = ((const ulonglong2*)g_table)[i];
        if ((unsigned)(v.x >> 32) == ep) {
            int ft = Tc - 1 - (int)(unsigned)v.x;
            atomicOr(&g_bits[ft >> 5], 1u << (ft & 31));
        }
        if ((unsigned)(v.y >> 32) == ep) {
            int ft = Tc - 1 - (int)(unsigned)v.y;
            atomicOr(&g_bits[ft >> 5], 1u << (ft & 31));
        }
    }
    gsync(GRID * 2);

    // ---- P3: scan1 (blocks 0..215) + last-done block does scan2 inline ----
    if (blockIdx.x < S1_BLOCKS) {
        int w = blockIdx.x * 256 + tid;
        int c = __popc(g_bits[w]);
        int incl = c;
#pragma unroll
        for (int d = 1; d < 32; d <<= 1) {
            int v = __shfl_up_sync(0xffffffffu, incl, d);
            if (lane >= d) incl += v;
        }
        if (lane == 31) wsum[wid] = incl;
        __syncthreads();
        if (wid == 0) {
            int v = (lane < 8) ? wsum[lane] : 0;
#pragma unroll
            for (int d = 1; d < 8; d <<= 1) {
                int u = __shfl_up_sync(0xffffffffu, v, d);
                if (lane >= d) v += u;
            }
            if (lane < 8) wsum[lane] = v;
        }
        __syncthreads();
        g_wordpre[w] = ((wid == 0) ? 0 : wsum[wid - 1]) + incl - c;
        if (tid == 255) g_bsum2[blockIdx.x] = wsum[7];

        // last-done block performs the 216-entry top scan
        __threadfence();
        __syncthreads();
        if (tid == 0) sh_pos = atomicAdd(&g_cnt, 1);
        __syncthreads();
        if (sh_pos == S1_BLOCKS - 1) {
            int v = (tid < S1_BLOCKS) ? g_bsum2[tid] : 0;
            sh[tid] = v;
            __syncthreads();
#pragma unroll
            for (int d = 1; d < 256; d <<= 1) {
                int u = (tid >= d) ? sh[tid - d] : 0;
                __syncthreads();
                sh[tid] += u;
                __syncthreads();
            }
            if (tid < S1_BLOCKS) g_bpre2[tid] = sh[tid] - v;
            if (tid == S1_BLOCKS - 1) {
                g_numout = sh[tid];
                out[6LL * Tc] = (float)sh[tid];          // num_out
            }
        }
    }
    gsync(GRID * 3);

    // ---- P4: assign rank per occupied key; write g_oi + out_key ----
    for (int i = gtid; i < TABLE_SIZE / 2; i += NTHR) {
        ulonglong2 vv = ((const ulonglong2*)g_table)[i];
#pragma unroll
        for (int j = 0; j < 2; j++) {
            unsigned long long v = j ? vv.y : vv.x;
            if ((unsigned)(v >> 32) != ep) continue;
            int ft  = Tc - 1 - (int)(unsigned)v;
            int key = i * 2 + j;
            int w = ft >> 5;
            unsigned mask = (1u << (ft & 31)) - 1u;
            int rank = g_bpre2[w >> 8] + g_wordpre[w] + __popc(g_bits[w] & mask);
            g_oi[key] = rank;
            int rem = key % BASE3;
            int xx = rem / (BASEc * BASEc) - SHIFTc;
            int yy = (rem / BASEc) % BASEc - SHIFTc;
            int zz = rem % BASEc - SHIFTc;
            float* p = out + 3LL * Tc + 3LL * rank;
            p[0] = (float)xx; p[1] = (float)yy; p[2] = (float)zz;
        }
    }
    gsync(GRID * 4);

    // ---- P5: in_idx / out_idx / rel_pos (float4) + out_key -1 padding ----
    int no = g_numout;
    for (int i = gtid; i < Tc / 4; i += NTHR) {
        int t0 = i * 4;
        float4 a, b, c;
#pragma unroll
        for (int j = 0; j < 4; j++) {
            int t   = t0 + j;
            int idx = t / Kc;
            int k   = t - idx * Kc;
            int key = g_keybase[idx] + c_delta[k];
            (&a.x)[j] = (float)(idx & (Nc - 1));
            (&b.x)[j] = (float)g_oi[key];
            (&c.x)[j] = (float)k;
        }
        ((float4*)out)[i]              = a;   // in_idx
        ((float4*)(out + 1LL * Tc))[i] = b;   // out_idx
        ((float4*)(out + 2LL * Tc))[i] = c;   // rel_pos

        if (t0 >= no) {                        // fully padded rows: 3x float4
            float4 m1 = make_float4(-1.f, -1.f, -1.f, -1.f);
            float4* p = (float4*)(out + 3LL * Tc + 12LL * i);
            p[0] = m1; p[1] = m1; p[2] = m1;
        } else if (t0 + 3 >= no) {             // boundary: scalar
#pragma unroll
            for (int j = 0; j < 4; j++) {
                int t = t0 + j;
                if (t >= no) {
                    float* p = out + 3LL * Tc + 3LL * t;
                    p[0] = -1.f; p[1] = -1.f; p[2] = -1.f;
                }
            }
        }
    }
}

extern "C" void kernel_launch(void* const* d_in, const int* in_sizes, int n_in,
                              void* d_out, int out_size) {
    // Identify inputs by SIZE: coordinates = [B,N,3] (3*BNc), batch = [B,N] (BNc).
    const int* coords = (const int*)d_in[0];
    const int* batch  = (const int*)d_in[n_in > 1 ? 1 : 0];
    for (int i = 0; i < n_in; i++) {
        if (in_sizes[i] == 3 * BNc) coords = (const int*)d_in[i];
        else if (in_sizes[i] == BNc) batch = (const int*)d_in[i];
    }
    float* out = (float*)d_out;
    long long osz = (long long)out_size;

    long long tail = osz - (6LL * Tc + 1);
    if (tail > 0) k_tail<<<512, 256>>>(out + 6LL * Tc + 1, tail);

    k_epoch<<<1, 1>>>();                 // bump epoch, rearm barrier + counter
    k_main<<<GRID, 256>>>(coords, batch, out);
}